// round 6
// baseline (speedup 1.0000x reference)
#include <cuda_runtime.h>
#include <math.h>

#define KGT 50
#define NA 3
#define NC 80
#define BMAX 16
#define NPART 1024          // >= total blocks (336 for B=16)

__device__ double g_pmain[NPART];
__device__ double g_phigh[NPART];
__device__ int    g_php[NPART];
__device__ int    g_count;       // zero-init; reset by finalize block each run

__device__ __forceinline__ float sigf(float x){ return 1.0f/(1.0f+expf(-x)); }

__device__ __forceinline__ float iou_f(float ax,float ay,float aw,float ah,
                                       float bx,float by,float bw,float bh){
    float tlx=fmaxf(ax-aw*0.5f, bx-bw*0.5f);
    float tly=fmaxf(ay-ah*0.5f, by-bh*0.5f);
    float brx=fminf(ax+aw*0.5f, bx+bw*0.5f);
    float bry=fminf(ay+ah*0.5f, by+bh*0.5f);
    float wx=fmaxf(brx-tlx,0.0f), wy=fmaxf(bry-tly,0.0f);
    float inter=wx*wy;
    return inter/(aw*ah + bw*bh - inter);
}

__global__ void __launch_bounds__(256) k_fused(
        const float* __restrict__ o0, const float* __restrict__ o1,
        const float* __restrict__ o2, const float* __restrict__ tgt,
        const float* __restrict__ anc,
        int W0, int W1, int W2, int B,
        int nb0, int nb1, int nb2,          // blocks per (scale,batch)
        float* __restrict__ outp){
    // ---- flat block -> (s, b, bx) ----
    int flat = blockIdx.x;
    int off1 = B*nb0, off2 = off1 + B*nb1;
    int s, b, bx;
    if (flat < off1){ s=0; b=flat/nb0; bx=flat - b*nb0; }
    else if (flat < off2){ s=1; int r=flat-off1; b=r/nb1; bx=r - b*nb1; }
    else { s=2; int r=flat-off2; b=r/nb2; bx=r - b*nb2; }
    const float* out  = (s==0) ? o0 : (s==1 ? o1 : o2);
    int W             = (s==0) ? W0 : (s==1 ? W1 : W2);
    const float* Aptr = anc + ((s==0) ? 12 : (s==1 ? 6 : 0));
    int HW = W*W, cells = NA*HW;
    int tid  = threadIdx.x;
    int lane = tid & 31, wid = tid >> 5;

    __shared__ float  s_raw[KGT*5];
    __shared__ float4 s_box[KGT];          // (l, t, r, b) ; invalid -> degenerate
    __shared__ float  s_ar07[KGT];         // 0.7*area ; invalid -> 0.7
    __shared__ float  s_ar[KGT];           // area     ; invalid -> 1.0
    __shared__ float  s_d[KGT][4];
    __shared__ int    s_v[KGT], s_f[KGT], s_idx[KGT], s_cls[KGT];
    __shared__ int    s_rec[512];
    __shared__ double s_wm[8], s_wh[8];
    __shared__ int    s_last;

    // ---- phase 0: coalesced GT load ----
    if (tid < KGT*5) s_raw[tid] = tgt[(size_t)b*KGT*5 + tid];
    s_rec[tid] = -1; s_rec[tid+256] = -1;
    __syncthreads();

    // ---- phase 1+2: per-GT box, validity, cell, best anchor, delta ----
    int my_valid = 0;
    if (tid < KGT){
        float t0=s_raw[tid*5+0], t1=s_raw[tid*5+1], t2=s_raw[tid*5+2],
              t3=s_raw[tid*5+3], t4=s_raw[tid*5+4];
        my_valid = ((t0+t1+t2+t3+t4) > 0.0f) ? 1 : 0;
        float gx=t0*(float)W, gy=t1*(float)W, gw=t2*(float)W, gh=t3*(float)W;
        s_v[tid]=my_valid;
        if (my_valid){
            s_box[tid] = make_float4(gx-gw*0.5f, gy-gh*0.5f, gx+gw*0.5f, gy+gh*0.5f);
            s_ar[tid]  = gw*gh;
            s_ar07[tid]= 0.7f*gw*gh;
        } else {
            s_box[tid] = make_float4(2e30f, 2e30f, -2e30f, -2e30f);
            s_ar[tid]  = 1.0f;
            s_ar07[tid]= 0.7f;
        }
        s_cls[tid]=(int)t4;
        int cx = min(max((int)floorf(gx),0), W-1);
        int cy = min(max((int)floorf(gy),0), W-1);
        int astar = 0; float best = -1e30f;
        #pragma unroll
        for (int a=0; a<NA; a++){
            float v = iou_f((float)cx+0.5f, (float)cy+0.5f, Aptr[a*2], Aptr[a*2+1],
                            gx, gy, gw, gh);
            if (v > best){ best = v; astar = a; }   // strict >: first max (argmax)
        }
        s_f[tid]   = (cy*W + cx)*NA + astar;        // dedup key
        s_idx[tid] = astar*HW + (cy*W + cx);        // cell index in thread layout
        s_d[tid][0] = gx - (float)cx;
        s_d[tid][1] = gy - (float)cy;
        s_d[tid][2] = gw / Aptr[astar*2+0];
        s_d[tid][3] = gh / Aptr[astar*2+1];
    }
    int numobj = __syncthreads_count(my_valid);

    // ---- phase 3: last-valid-wins dedup + scatter into this block's 512 range ----
    if (tid < KGT && my_valid){
        int f = s_f[tid], win = 1;
        for (int k2 = tid+1; k2 < KGT; k2++)
            if (s_v[k2] && s_f[k2]==f){ win = 0; break; }
        if (win){
            int rel = s_idx[tid] - bx*512;
            if (rel >= 0 && rel < 512) s_rec[rel] = tid;
        }
    }
    __syncthreads();

    // ---- phase 4: two cells per thread ----
    int idx0 = bx*512 + tid;
    int idx1 = idx0 + 256;
    bool act0 = (idx0 < cells), act1 = (idx1 < cells);
    int ci0 = act0 ? idx0 : 0;
    int ci1 = act1 ? idx1 : 0;

    int a0i = ci0 / HW, hw0 = ci0 - a0i*HW;
    int a1i = ci1 / HW, hw1 = ci1 - a1i*HW;
    const float* p0 = out + (size_t)(b*255 + a0i*85)*HW + hw0;
    const float* p1 = out + (size_t)(b*255 + a1i*85)*HW + hw1;

    float u0 = p0[0], u1 = p0[(size_t)HW], u2 = p0[(size_t)2*HW],
          u3 = p0[(size_t)3*HW], u4 = p0[(size_t)4*HW];
    float q0 = p1[0], q1 = p1[(size_t)HW], q2 = p1[(size_t)2*HW],
          q3 = p1[(size_t)3*HW], q4 = p1[(size_t)4*HW];

    float sx0=sigf(u0), sy0=sigf(u1), ew0=expf(u2), eh0=expf(u3), cf0=sigf(u4);
    float sx1=sigf(q0), sy1=sigf(q1), ew1=expf(q2), eh1=expf(q3), cf1=sigf(q4);

    float A00=Aptr[a0i*2], A01=Aptr[a0i*2+1];
    float A10=Aptr[a1i*2], A11=Aptr[a1i*2+1];

    float px0 = sx0 + (float)(hw0 % W), py0 = sy0 + (float)(hw0 / W);
    float px1 = sx1 + (float)(hw1 % W), py1 = sy1 + (float)(hw1 / W);
    float pw0 = ew0*A00, ph0 = eh0*A01, pw1 = ew1*A10, ph1 = eh1*A11;
    float pl0=px0-pw0*0.5f, pr0=px0+pw0*0.5f, pt0=py0-ph0*0.5f, pb0=py0+ph0*0.5f;
    float pl1=px1-pw1*0.5f, pr1=px1+pw1*0.5f, pt1=py1-ph1*0.5f, pb1=py1+ph1*0.5f;
    float pa0 = pw0*ph0, pa1 = pw1*ph1;

    // hot loop: one LDS.128 + one LDS per k serves two cells; no div, no branch
    float ml0 = -1e30f, ml1 = -1e30f;
    #pragma unroll 5
    for (int k=0;k<KGT;k++){
        float4 bb = s_box[k];
        float c  = s_ar07[k];
        float wx0 = fminf(pr0, bb.z) - fmaxf(pl0, bb.x);
        float wy0 = fminf(pb0, bb.w) - fmaxf(pt0, bb.y);
        float wx1 = fminf(pr1, bb.z) - fmaxf(pl1, bb.x);
        float wy1 = fminf(pb1, bb.w) - fmaxf(pt1, bb.y);
        wx0 = fmaxf(wx0, 0.0f); wy0 = fmaxf(wy0, 0.0f);
        wx1 = fmaxf(wx1, 0.0f); wy1 = fmaxf(wy1, 0.0f);
        float i0 = wx0*wy0, i1 = wx1*wy1;
        ml0 = fmaxf(ml0, fmaf(i0, 1.7f, -c));
        ml1 = fmaxf(ml1, fmaf(i1, 1.7f, -c));
    }
    bool ge0 = (ml0 >= 0.7f*pa0), gt0 = (ml0 > 0.7f*pa0);
    bool ge1 = (ml1 >= 0.7f*pa1), gt1 = (ml1 > 0.7f*pa1);

    double vm = 0.0, vh = 0.0;

    // --- cell 0 epilogue ---
    if (act0){
        int rec = s_rec[tid];
        if (rec >= 0){
            float m = -1.0f;
            for (int k=0;k<KGT;k++){
                float4 bb = s_box[k];
                float wx = fmaxf(fminf(pr0, bb.z) - fmaxf(pl0, bb.x), 0.0f);
                float wy = fmaxf(fminf(pb0, bb.w) - fmaxf(pt0, bb.y), 0.0f);
                float inter = wx*wy;
                m = fmaxf(m, inter / (pa0 + s_ar[k] - inter));
            }
            float di = 5.0f*(cf0 - m);
            float dx = sx0 - s_d[rec][0];
            float dy = sy0 - s_d[rec][1];
            float dw = ew0 - s_d[rec][2];
            float dh = eh0 - s_d[rec][3];
            float mx = -1e30f;
            for (int c=0;c<NC;c++) mx = fmaxf(mx, p0[(size_t)(5+c)*HW]);
            float sm = 0.0f;
            for (int c=0;c<NC;c++) sm += expf(p0[(size_t)(5+c)*HW] - mx);
            float lse = mx + logf(sm);
            float tl  = p0[(size_t)(5+s_cls[rec])*HW];
            vm += 0.5*(double)(di*di)
                + 0.5*(double)(dx*dx + dy*dy + dw*dw + dh*dh)
                + (double)(lse - tl);
        } else if (numobj > 0){
            double c2s = 0.5*(double)(cf0*cf0);
            vm += c2s;
            if (ge0) vh += c2s;
        }
    }
    // --- cell 1 epilogue ---
    if (act1){
        int rec = s_rec[tid+256];
        if (rec >= 0){
            float m = -1.0f;
            for (int k=0;k<KGT;k++){
                float4 bb = s_box[k];
                float wx = fmaxf(fminf(pr1, bb.z) - fmaxf(pl1, bb.x), 0.0f);
                float wy = fmaxf(fminf(pb1, bb.w) - fmaxf(pt1, bb.y), 0.0f);
                float inter = wx*wy;
                m = fmaxf(m, inter / (pa1 + s_ar[k] - inter));
            }
            float di = 5.0f*(cf1 - m);
            float dx = sx1 - s_d[rec][0];
            float dy = sy1 - s_d[rec][1];
            float dw = ew1 - s_d[rec][2];
            float dh = eh1 - s_d[rec][3];
            float mx = -1e30f;
            for (int c=0;c<NC;c++) mx = fmaxf(mx, p1[(size_t)(5+c)*HW]);
            float sm = 0.0f;
            for (int c=0;c<NC;c++) sm += expf(p1[(size_t)(5+c)*HW] - mx);
            float lse = mx + logf(sm);
            float tl  = p1[(size_t)(5+s_cls[rec])*HW];
            vm += 0.5*(double)(di*di)
                + 0.5*(double)(dx*dx + dy*dy + dw*dw + dh*dh)
                + (double)(lse - tl);
        } else if (numobj > 0){
            double c2s = 0.5*(double)(cf1*cf1);
            vm += c2s;
            if (ge1) vh += c2s;
        }
    }
    int hpAll = __syncthreads_or((act0 && gt0) || (act1 && gt1));

    // ---- block reduction (warp shuffles, deterministic) ----
    #pragma unroll
    for (int off=16; off>0; off>>=1){
        vm += __shfl_down_sync(0xffffffffu, vm, off);
        vh += __shfl_down_sync(0xffffffffu, vh, off);
    }
    if (lane == 0){ s_wm[wid]=vm; s_wh[wid]=vh; }
    __syncthreads();
    if (tid == 0){
        double bm=0.0, bh=0.0;
        #pragma unroll
        for (int w=0; w<8; w++){ bm+=s_wm[w]; bh+=s_wh[w]; }
        g_pmain[flat]=bm; g_phigh[flat]=bh; g_php[flat]=hpAll;
        __threadfence();
        int old = atomicAdd(&g_count, 1);
        s_last = (old == (int)gridDim.x - 1) ? 1 : 0;
    }
    __syncthreads();

    // ---- finalize by the last block ----
    if (s_last){
        __threadfence();
        int ngroups = 3*B;
        double v = 0.0;
        if (tid < ngroups){
            int gs = tid / B, gb = tid - gs*B;
            int nb  = (gs==0) ? nb0 : (gs==1 ? nb1 : nb2);
            int gbase = ((gs>0)? B*nb0 : 0) + ((gs>1)? B*nb1 : 0) + gb*nb;
            double m = 0.0, h = 0.0; int hp = 0;
            for (int j=0;j<nb;j++){
                m += g_pmain[gbase+j];
                h += g_phigh[gbase+j];
                hp |= g_php[gbase+j];
            }
            v = m - (hp ? h : 0.0);
        }
        #pragma unroll
        for (int off=16; off>0; off>>=1) v += __shfl_down_sync(0xffffffffu, v, off);
        if (lane == 0) s_wm[wid] = v;
        __syncthreads();
        if (tid == 0){
            double t = 0.0;
            #pragma unroll
            for (int w=0; w<8; w++) t += s_wm[w];
            outp[0] = (float)(t / ((double)B * 3.0));
            g_count = 0;
        }
    }
}

extern "C" void kernel_launch(void* const* d_in, const int* in_sizes, int n_in,
                              void* d_out, int out_size){
    const float* o0  = (const float*)d_in[0];
    const float* o1  = (const float*)d_in[1];
    const float* o2  = (const float*)d_in[2];
    const float* tgt = (const float*)d_in[3];
    const float* anc = (const float*)d_in[4];
    int B = in_sizes[3] / (KGT*5);
    int Ws[3], nb[3];
    for (int i=0;i<3;i++){
        int hw = in_sizes[i] / (B*255);
        int w = 1; while (w*w < hw) w++;
        Ws[i] = w;
        nb[i] = (NA*hw + 511) / 512;
    }
    int total = B*(nb[0]+nb[1]+nb[2]);
    k_fused<<<total, 256>>>(o0, o1, o2, tgt, anc,
                            Ws[0], Ws[1], Ws[2], B,
                            nb[0], nb[1], nb[2], (float*)d_out);
}

// round 7
// speedup vs baseline: 1.6644x; 1.6644x over previous
#include <cuda_runtime.h>
#include <math.h>

#define KGT 50
#define NA 3
#define NC 80
#define BMAX 16
#define NPART 1024          // >= total blocks (336 for B=16)

__device__ double g_pmain[NPART];
__device__ double g_phigh[NPART];
__device__ int    g_php[NPART];
__device__ int    g_count;       // zero-init; reset by finalize block each run

__device__ __forceinline__ float sigf(float x){ return 1.0f/(1.0f+expf(-x)); }

__device__ __forceinline__ float iou_f(float ax,float ay,float aw,float ah,
                                       float bx,float by,float bw,float bh){
    float tlx=fmaxf(ax-aw*0.5f, bx-bw*0.5f);
    float tly=fmaxf(ay-ah*0.5f, by-bh*0.5f);
    float brx=fminf(ax+aw*0.5f, bx+bw*0.5f);
    float bry=fminf(ay+ah*0.5f, by+bh*0.5f);
    float wx=fmaxf(brx-tlx,0.0f), wy=fmaxf(bry-tly,0.0f);
    float inter=wx*wy;
    return inter/(aw*ah + bw*bh - inter);
}

__global__ void __launch_bounds__(256) k_fused(
        const float* __restrict__ o0, const float* __restrict__ o1,
        const float* __restrict__ o2, const float* __restrict__ tgt,
        const float* __restrict__ anc,
        int W0, int W1, int W2, int B,
        int nb0, int nb1, int nb2,
        float* __restrict__ outp){
    // ---- flat block -> (s, b, bx) ----
    int flat = blockIdx.x;
    int off1 = B*nb0, off2 = off1 + B*nb1;
    int s, b, bx;
    if (flat < off1){ s=0; b=flat/nb0; bx=flat - b*nb0; }
    else if (flat < off2){ s=1; int r=flat-off1; b=r/nb1; bx=r - b*nb1; }
    else { s=2; int r=flat-off2; b=r/nb2; bx=r - b*nb2; }
    const float* out  = (s==0) ? o0 : (s==1 ? o1 : o2);
    int W             = (s==0) ? W0 : (s==1 ? W1 : W2);
    const float* Aptr = anc + ((s==0) ? 12 : (s==1 ? 6 : 0));
    int HW = W*W, cells = NA*HW;
    int tid  = threadIdx.x;
    int lane = tid & 31, wid = tid >> 5;

    __shared__ float  s_raw[KGT*5];
    __shared__ float4 s_box[KGT];          // (l,t,r,b); invalid -> degenerate
    __shared__ float  s_ar07[KGT];         // 0.7*area ; invalid -> 0.7
    __shared__ float  s_ar[KGT];           // area     ; invalid -> 1.0
    __shared__ float  s_d[KGT][4];
    __shared__ int    s_v[KGT], s_f[KGT], s_idx[KGT], s_cls[KGT];
    __shared__ int    s_winflag[KGT];      // winner AND cell in this block's range
    __shared__ int    s_rec[512];          // 1 if cell is a winner cell (excl. noobj)
    __shared__ double s_wm[8], s_wh[8];
    __shared__ int    s_last;

    // ---- phase 0: coalesced GT load ----
    if (tid < KGT*5) s_raw[tid] = tgt[(size_t)b*KGT*5 + tid];
    s_rec[tid] = 0; s_rec[tid+256] = 0;
    if (tid < KGT) s_winflag[tid] = 0;
    __syncthreads();

    // ---- phase 1+2: per-GT box, validity, cell, best anchor, delta ----
    int my_valid = 0;
    if (tid < KGT){
        float t0=s_raw[tid*5+0], t1=s_raw[tid*5+1], t2=s_raw[tid*5+2],
              t3=s_raw[tid*5+3], t4=s_raw[tid*5+4];
        my_valid = ((t0+t1+t2+t3+t4) > 0.0f) ? 1 : 0;
        float gx=t0*(float)W, gy=t1*(float)W, gw=t2*(float)W, gh=t3*(float)W;
        s_v[tid]=my_valid;
        if (my_valid){
            s_box[tid] = make_float4(gx-gw*0.5f, gy-gh*0.5f, gx+gw*0.5f, gy+gh*0.5f);
            s_ar[tid]  = gw*gh;
            s_ar07[tid]= 0.7f*gw*gh;
        } else {
            s_box[tid] = make_float4(2e30f, 2e30f, -2e30f, -2e30f);
            s_ar[tid]  = 1.0f;
            s_ar07[tid]= 0.7f;
        }
        s_cls[tid]=(int)t4;
        int cx = min(max((int)floorf(gx),0), W-1);
        int cy = min(max((int)floorf(gy),0), W-1);
        int astar = 0; float best = -1e30f;
        #pragma unroll
        for (int a=0; a<NA; a++){
            float v = iou_f((float)cx+0.5f, (float)cy+0.5f, Aptr[a*2], Aptr[a*2+1],
                            gx, gy, gw, gh);
            if (v > best){ best = v; astar = a; }   // strict >: first max (argmax)
        }
        s_f[tid]   = (cy*W + cx)*NA + astar;        // dedup key
        s_idx[tid] = astar*HW + (cy*W + cx);        // cell index in thread layout
        s_d[tid][0] = gx - (float)cx;
        s_d[tid][1] = gy - (float)cy;
        s_d[tid][2] = gw / Aptr[astar*2+0];
        s_d[tid][3] = gh / Aptr[astar*2+1];
    }
    int numobj = __syncthreads_count(my_valid);

    // ---- phase 3: last-valid-wins dedup; flag winners owned by this block ----
    if (tid < KGT && my_valid){
        int f = s_f[tid], win = 1;
        for (int k2 = tid+1; k2 < KGT; k2++)
            if (s_v[k2] && s_f[k2]==f){ win = 0; break; }
        if (win){
            int rel = s_idx[tid] - bx*512;
            if (rel >= 0 && rel < 512){ s_rec[rel] = 1; s_winflag[tid] = 1; }
        }
    }
    __syncthreads();

    // ---- phase 4: two cells per thread, uniform branch-free noobj work ----
    int idx0 = bx*512 + tid;
    int idx1 = idx0 + 256;
    bool act0 = (idx0 < cells), act1 = (idx1 < cells);
    int ci0 = act0 ? idx0 : 0;
    int ci1 = act1 ? idx1 : 0;

    int a0i = ci0 / HW, hw0 = ci0 - a0i*HW;
    int a1i = ci1 / HW, hw1 = ci1 - a1i*HW;
    const float* p0 = out + (size_t)(b*255 + a0i*85)*HW + hw0;
    const float* p1 = out + (size_t)(b*255 + a1i*85)*HW + hw1;

    float u0 = p0[0], u1 = p0[(size_t)HW], u2 = p0[(size_t)2*HW],
          u3 = p0[(size_t)3*HW], u4 = p0[(size_t)4*HW];
    float q0 = p1[0], q1 = p1[(size_t)HW], q2 = p1[(size_t)2*HW],
          q3 = p1[(size_t)3*HW], q4 = p1[(size_t)4*HW];

    float sx0=sigf(u0), sy0=sigf(u1), ew0=expf(u2), eh0=expf(u3), cf0=sigf(u4);
    float sx1=sigf(q0), sy1=sigf(q1), ew1=expf(q2), eh1=expf(q3), cf1=sigf(q4);

    float px0 = sx0 + (float)(hw0 % W), py0 = sy0 + (float)(hw0 / W);
    float px1 = sx1 + (float)(hw1 % W), py1 = sy1 + (float)(hw1 / W);
    float pw0 = ew0*Aptr[a0i*2], ph0 = eh0*Aptr[a0i*2+1];
    float pw1 = ew1*Aptr[a1i*2], ph1 = eh1*Aptr[a1i*2+1];
    float pl0=px0-pw0*0.5f, pr0=px0+pw0*0.5f, pt0=py0-ph0*0.5f, pb0=py0+ph0*0.5f;
    float pl1=px1-pw1*0.5f, pr1=px1+pw1*0.5f, pt1=py1-ph1*0.5f, pb1=py1+ph1*0.5f;
    float pa0 = pw0*ph0, pa1 = pw1*ph1;

    float ml0 = -1e30f, ml1 = -1e30f;
    #pragma unroll 5
    for (int k=0;k<KGT;k++){
        float4 bb = s_box[k];
        float c  = s_ar07[k];
        float wx0 = fminf(pr0, bb.z) - fmaxf(pl0, bb.x);
        float wy0 = fminf(pb0, bb.w) - fmaxf(pt0, bb.y);
        float wx1 = fminf(pr1, bb.z) - fmaxf(pl1, bb.x);
        float wy1 = fminf(pb1, bb.w) - fmaxf(pt1, bb.y);
        wx0 = fmaxf(wx0, 0.0f); wy0 = fmaxf(wy0, 0.0f);
        wx1 = fmaxf(wx1, 0.0f); wy1 = fmaxf(wy1, 0.0f);
        ml0 = fmaxf(ml0, fmaf(wx0*wy0, 1.7f, -c));
        ml1 = fmaxf(ml1, fmaf(wx1*wy1, 1.7f, -c));
    }
    bool ge0 = (ml0 >= 0.7f*pa0), gt0 = (ml0 > 0.7f*pa0);
    bool ge1 = (ml1 >= 0.7f*pa1), gt1 = (ml1 > 0.7f*pa1);

    double vm = 0.0, vh = 0.0;
    if (act0 && !s_rec[tid] && numobj > 0){
        double c2s = 0.5*(double)(cf0*cf0);
        vm += c2s; if (ge0) vh += c2s;
    }
    if (act1 && !s_rec[tid+256] && numobj > 0){
        double c2s = 0.5*(double)(cf1*cf1);
        vm += c2s; if (ge1) vh += c2s;
    }
    int hpAll = __syncthreads_or((act0 && gt0) || (act1 && gt1));

    // warp reduce phase-4 sums into lane 0
    #pragma unroll
    for (int off=16; off>0; off>>=1){
        vm += __shfl_down_sync(0xffffffffu, vm, off);
        vh += __shfl_down_sync(0xffffffffu, vh, off);
    }

    // ---- phase 5: warp-cooperative positive-cell loss (warp w -> GTs w, w+8, ...) ----
    #pragma unroll 1
    for (int k = wid; k < KGT; k += 8){
        if (!s_winflag[k]) continue;                 // warp-uniform
        int ci = s_idx[k];
        int a = ci / HW, hw = ci - a*HW;
        const float* bp = out + (size_t)(b*255 + a*85)*HW + hw;
        float v0 = bp[0], v1 = bp[(size_t)HW], v2 = bp[(size_t)2*HW],
              v3 = bp[(size_t)3*HW], v4 = bp[(size_t)4*HW];
        float sx = sigf(v0), sy = sigf(v1), ew = expf(v2), eh = expf(v3), cf = sigf(v4);
        float px = sx + (float)(hw % W), py = sy + (float)(hw / W);
        float pw = ew*Aptr[a*2], ph = eh*Aptr[a*2+1];
        float pl = px - pw*0.5f, pr = px + pw*0.5f;
        float pt = py - ph*0.5f, pb = py + ph*0.5f;
        float pa = pw*ph;
        // exact max-IoU: GT j = lane and lane+32 (invalid GTs give 0 >= -1, safe)
        float mloc;
        {
            float4 bb = s_box[lane];
            float wx = fmaxf(fminf(pr, bb.z) - fmaxf(pl, bb.x), 0.0f);
            float wy = fmaxf(fminf(pb, bb.w) - fmaxf(pt, bb.y), 0.0f);
            float inter = wx*wy;
            mloc = inter / (pa + s_ar[lane] - inter);
            int j2 = lane + 32;
            if (j2 < KGT){
                float4 b2 = s_box[j2];
                float wx2 = fmaxf(fminf(pr, b2.z) - fmaxf(pl, b2.x), 0.0f);
                float wy2 = fmaxf(fminf(pb, b2.w) - fmaxf(pt, b2.y), 0.0f);
                float i2 = wx2*wy2;
                mloc = fmaxf(mloc, i2 / (pa + s_ar[j2] - i2));
            }
        }
        #pragma unroll
        for (int off=16; off>0; off>>=1)
            mloc = fmaxf(mloc, __shfl_xor_sync(0xffffffffu, mloc, off));
        // class LSE: lanes handle classes lane, lane+32, lane+64
        float c0v = bp[(size_t)(5+lane)*HW];
        float c1v = bp[(size_t)(5+lane+32)*HW];
        float c2v = (lane+64 < NC) ? bp[(size_t)(5+lane+64)*HW] : -1e30f;
        float mx = fmaxf(fmaxf(c0v, c1v), c2v);
        #pragma unroll
        for (int off=16; off>0; off>>=1)
            mx = fmaxf(mx, __shfl_xor_sync(0xffffffffu, mx, off));
        float sm = expf(c0v-mx) + expf(c1v-mx) + ((lane+64 < NC) ? expf(c2v-mx) : 0.0f);
        #pragma unroll
        for (int off=16; off>0; off>>=1)
            sm += __shfl_xor_sync(0xffffffffu, sm, off);
        if (lane == 0){
            float lse = mx + logf(sm);
            float tl  = bp[(size_t)(5+s_cls[k])*HW];
            float di  = 5.0f*(cf - mloc);
            float dx = sx - s_d[k][0];
            float dy = sy - s_d[k][1];
            float dw = ew - s_d[k][2];
            float dh = eh - s_d[k][3];
            vm += 0.5*(double)(di*di)
                + 0.5*(double)(dx*dx + dy*dy + dw*dw + dh*dh)
                + (double)(lse - tl);
        }
    }

    if (lane == 0){ s_wm[wid]=vm; s_wh[wid]=vh; }
    __syncthreads();
    if (tid == 0){
        double bm=0.0, bh=0.0;
        #pragma unroll
        for (int w=0; w<8; w++){ bm+=s_wm[w]; bh+=s_wh[w]; }
        g_pmain[flat]=bm; g_phigh[flat]=bh; g_php[flat]=hpAll;
        __threadfence();
        int old = atomicAdd(&g_count, 1);
        s_last = (old == (int)gridDim.x - 1) ? 1 : 0;
    }
    __syncthreads();

    // ---- finalize by the last block ----
    if (s_last){
        __threadfence();
        int ngroups = 3*B;
        double v = 0.0;
        if (tid < ngroups){
            int gs = tid / B, gb = tid - gs*B;
            int nb  = (gs==0) ? nb0 : (gs==1 ? nb1 : nb2);
            int gbase = ((gs>0)? B*nb0 : 0) + ((gs>1)? B*nb1 : 0) + gb*nb;
            double m = 0.0, h = 0.0; int hp = 0;
            for (int j=0;j<nb;j++){
                m += g_pmain[gbase+j];
                h += g_phigh[gbase+j];
                hp |= g_php[gbase+j];
            }
            v = m - (hp ? h : 0.0);
        }
        #pragma unroll
        for (int off=16; off>0; off>>=1) v += __shfl_down_sync(0xffffffffu, v, off);
        if (lane == 0) s_wm[wid] = v;
        __syncthreads();
        if (tid == 0){
            double t = 0.0;
            #pragma unroll
            for (int w=0; w<8; w++) t += s_wm[w];
            outp[0] = (float)(t / ((double)B * 3.0));
            g_count = 0;
        }
    }
}

extern "C" void kernel_launch(void* const* d_in, const int* in_sizes, int n_in,
                              void* d_out, int out_size){
    const float* o0  = (const float*)d_in[0];
    const float* o1  = (const float*)d_in[1];
    const float* o2  = (const float*)d_in[2];
    const float* tgt = (const float*)d_in[3];
    const float* anc = (const float*)d_in[4];
    int B = in_sizes[3] / (KGT*5);
    int Ws[3], nb[3];
    for (int i=0;i<3;i++){
        int hw = in_sizes[i] / (B*255);
        int w = 1; while (w*w < hw) w++;
        Ws[i] = w;
        nb[i] = (NA*hw + 511) / 512;
    }
    int total = B*(nb[0]+nb[1]+nb[2]);
    k_fused<<<total, 256>>>(o0, o1, o2, tgt, anc,
                            Ws[0], Ws[1], Ws[2], B,
                            nb[0], nb[1], nb[2], (float*)d_out);
}